// round 6
// baseline (speedup 1.0000x reference)
#include <cuda_runtime.h>

#define TW 32            // output tile width
#define TH 32            // output tile height
#define IR (TH + 10)     // 42 intermediate (horizontally-convolved) rows
#define IW (TW + 10)     // 42 input tile cols
#define ISTR 43          // input tile row stride (floats) — odd to avoid conflicts
#define HS 33            // intermediate buffer row stride (floats)
#define WDIM 512
#define HDIM 512
#define NBLOCKS (16 * 16 * 48)

// Normalized 1-D Gaussian, sigma=1.5, 11 taps. __device__ constexpr so it is
// visible in device code; all accesses are at compile-time indices after full
// unroll, so ptxas folds taps into FFMA-imm (rt_SMSP=1, 2x tput of 3-reg FFMA).
__device__ constexpr float GW[11] = {
    0.00102838f, 0.00759875f, 0.03600077f, 0.10936125f, 0.21300531f,
    0.26601172f,
    0.21300531f, 0.10936125f, 0.03600077f, 0.00759875f, 0.00102838f};

__device__ float g_partials[NBLOCKS];

__global__ __launch_bounds__(256) void ssim_main(
    const float* __restrict__ pred, const float* __restrict__ targ) {
  __shared__ float sp[IR * ISTR];
  __shared__ float st[IR * ISTR];
  __shared__ float hbuf[5][IR * HS];
  __shared__ float red[8];

  const int tid = threadIdx.x;
  const int gx0 = blockIdx.x * TW - 5;
  const int gy0 = blockIdx.y * TH - 5;
  const size_t plane_off = (size_t)blockIdx.z * (WDIM * HDIM);
  const float* __restrict__ pbase = pred + plane_off;
  const float* __restrict__ tbase = targ + plane_off;

  // ---- Stage A: stage input tiles with zero halo (SAME zero padding) ----
  for (int i = tid; i < IR * IW; i += 256) {
    int r = i / IW;
    int c = i - r * IW;
    int gy = gy0 + r, gx = gx0 + c;
    float pv = 0.f, tv = 0.f;
    if ((unsigned)gy < (unsigned)HDIM && (unsigned)gx < (unsigned)WDIM) {
      int idx = gy * WDIM + gx;
      pv = pbase[idx];
      tv = tbase[idx];
    }
    sp[r * ISTR + c] = pv;
    st[r * ISTR + c] = tv;
  }
  __syncthreads();

  // ---- Stage B: horizontal conv of {p, t, p^2, t^2, p*t} ----
  // 168 tasks: 42 rows x 4 groups of 8 columns, sliding read window.
  if (tid < IR * 4) {
    const int row = tid >> 2;
    const int cb = (tid & 3) * 8;
    const float* __restrict__ pr = &sp[row * ISTR + cb];
    const float* __restrict__ tr = &st[row * ISTR + cb];
    float hp[8], ht[8], hpp[8], htt[8], hpt[8];
#pragma unroll
    for (int j = 0; j < 8; ++j) {
      hp[j] = 0.f; ht[j] = 0.f; hpp[j] = 0.f; htt[j] = 0.f; hpt[j] = 0.f;
    }
#pragma unroll
    for (int k = 0; k < 18; ++k) {
      float p = pr[k], t = tr[k];
      float pp = p * p, tt = t * t, pt = p * t;
#pragma unroll
      for (int j = 0; j < 8; ++j) {
        const int tap = k - j;
        if (tap >= 0 && tap <= 10) {
          const float w = GW[tap];
          hp[j] += w * p;
          ht[j] += w * t;
          hpp[j] += w * pp;
          htt[j] += w * tt;
          hpt[j] += w * pt;
        }
      }
    }
#pragma unroll
    for (int j = 0; j < 8; ++j) {
      const int o = row * HS + cb + j;
      hbuf[0][o] = hp[j];
      hbuf[1][o] = ht[j];
      hbuf[2][o] = hpp[j];
      hbuf[3][o] = htt[j];
      hbuf[4][o] = hpt[j];
    }
  }
  __syncthreads();

  // ---- Stage C: vertical conv + fused SSIM epilogue ----
  // thread -> (col = lane, 4 consecutive output rows)
  const int col = tid & 31;
  const int rb = (tid >> 5) * 4;  // 0..28
  float acc[4][5];
#pragma unroll
  for (int j = 0; j < 4; ++j)
#pragma unroll
    for (int ch = 0; ch < 5; ++ch) acc[j][ch] = 0.f;

#pragma unroll
  for (int ir = 0; ir < 14; ++ir) {
    const int o = (rb + ir) * HS + col;
    const float v0 = hbuf[0][o];
    const float v1 = hbuf[1][o];
    const float v2 = hbuf[2][o];
    const float v3 = hbuf[3][o];
    const float v4 = hbuf[4][o];
#pragma unroll
    for (int j = 0; j < 4; ++j) {
      const int tap = ir - j;
      if (tap >= 0 && tap <= 10) {
        const float w = GW[tap];
        acc[j][0] += w * v0;
        acc[j][1] += w * v1;
        acc[j][2] += w * v2;
        acc[j][3] += w * v3;
        acc[j][4] += w * v4;
      }
    }
  }

  float lsum = 0.f;
#pragma unroll
  for (int j = 0; j < 4; ++j) {
    const float mp = acc[j][0];
    const float mt = acc[j][1];
    const float mp2 = mp * mp;
    const float mt2 = mt * mt;
    const float mct = mp * mt;
    const float sgp = acc[j][2] - mp2;
    const float sgt = acc[j][3] - mt2;
    const float sgc = acc[j][4] - mct;
    const float num = (2.0f * mct + 1e-4f) * (2.0f * sgc + 9e-4f);
    const float den = (mp2 + mt2 + 1e-4f) * (sgp + sgt + 9e-4f);
    lsum += __fdividef(num, den);
  }

  // ---- fixed-order block reduction (deterministic) ----
#pragma unroll
  for (int o = 16; o > 0; o >>= 1) lsum += __shfl_down_sync(0xffffffffu, lsum, o);
  if ((tid & 31) == 0) red[tid >> 5] = lsum;
  __syncthreads();
  if (tid < 8) {
    float v = red[tid];
    v += __shfl_down_sync(0x000000ffu, v, 4);
    v += __shfl_down_sync(0x000000ffu, v, 2);
    v += __shfl_down_sync(0x000000ffu, v, 1);
    if (tid == 0) {
      const int bid =
          (blockIdx.z * gridDim.y + blockIdx.y) * gridDim.x + blockIdx.x;
      g_partials[bid] = v;
    }
  }
}

__global__ __launch_bounds__(256) void ssim_finalize(float* __restrict__ out) {
  __shared__ double red[8];
  double s = 0.0;
  for (int i = threadIdx.x; i < NBLOCKS; i += 256) s += (double)g_partials[i];
#pragma unroll
  for (int o = 16; o > 0; o >>= 1) s += __shfl_down_sync(0xffffffffu, s, o);
  if ((threadIdx.x & 31) == 0) red[threadIdx.x >> 5] = s;
  __syncthreads();
  if (threadIdx.x == 0) {
    double t = 0.0;
#pragma unroll
    for (int i = 0; i < 8; ++i) t += red[i];
    out[0] = (float)(1.0 - t / 12582912.0);  // 16*3*512*512
  }
}

extern "C" void kernel_launch(void* const* d_in, const int* in_sizes, int n_in,
                              void* d_out, int out_size) {
  (void)in_sizes; (void)n_in; (void)out_size;
  const float* pred = (const float*)d_in[0];
  const float* targ = (const float*)d_in[1];
  dim3 grid(WDIM / TW, HDIM / TH, 48);
  ssim_main<<<grid, 256>>>(pred, targ);
  ssim_finalize<<<1, 256>>>((float*)d_out);
}